// round 15
// baseline (speedup 1.0000x reference)
#include <cuda_runtime.h>
#include <cuda_bf16.h>
#include <math.h>
#include <stdint.h>
#include <cstdint>

// Problem constants
#define S_LEN 4096
#define D_MODEL 1024
#define NUM_HEADS 16
#define DK 64
#define NUM_BUCKETS 32
#define LOG2E 1.4426950408889634f

// Scratch (device globals: no allocation allowed)
__device__ float g_Q[NUM_HEADS * S_LEN * DK];
__device__ float g_K[NUM_HEADS * S_LEN * DK];
__device__ float g_V[NUM_HEADS * S_LEN * DK];
__device__ float g_bias[NUM_HEADS * S_LEN];

// tf32-rounded fp32 operands
__device__ float g_XT[3 * S_LEN * D_MODEL];        // rounded inputs q/k/v
__device__ float g_WT[4 * D_MODEL * D_MODEL];      // transposed rounded weights [n][k]
__device__ float g_CT[S_LEN * D_MODEL];            // rounded attention context

// ---------------------------------------------------------------------------
// helpers
// ---------------------------------------------------------------------------
__device__ __forceinline__ float tf32_round(float x) {
    unsigned u;
    asm("cvt.rna.tf32.f32 %0, %1;" : "=r"(u) : "f"(x));
    return __uint_as_float(u);
}

__device__ __forceinline__ void mma_tf32(float c[4],
                                         unsigned a0, unsigned a1, unsigned a2, unsigned a3,
                                         unsigned b0, unsigned b1) {
    asm volatile(
        "mma.sync.aligned.m16n8k8.row.col.f32.tf32.tf32.f32 "
        "{%0,%1,%2,%3}, {%4,%5,%6,%7}, {%8,%9}, {%0,%1,%2,%3};"
        : "+f"(c[0]), "+f"(c[1]), "+f"(c[2]), "+f"(c[3])
        : "r"(a0), "r"(a1), "r"(a2), "r"(a3), "r"(b0), "r"(b1));
}

__device__ __forceinline__ void ldsm4(unsigned &r0, unsigned &r1, unsigned &r2,
                                      unsigned &r3, uint32_t addr) {
    asm volatile("ldmatrix.sync.aligned.m8n8.x4.shared.b16 {%0,%1,%2,%3}, [%4];"
                 : "=r"(r0), "=r"(r1), "=r"(r2), "=r"(r3) : "r"(addr));
}

__device__ __forceinline__ void cpa16(uint32_t saddr, const void* g) {
    asm volatile("cp.async.cg.shared.global [%0], [%1], 16;" :: "r"(saddr), "l"(g));
}
__device__ __forceinline__ void cpa4(uint32_t saddr, const void* g) {
    asm volatile("cp.async.ca.shared.global [%0], [%1], 4;" :: "r"(saddr), "l"(g));
}
__device__ __forceinline__ void cpa_commit() {
    asm volatile("cp.async.commit_group;");
}
template <int N>
__device__ __forceinline__ void cpa_wait() {
    asm volatile("cp.async.wait_group %0;" :: "n"(N));
}

// ---------------------------------------------------------------------------
// Fused prep kernel: grid.z selects the job.
// ---------------------------------------------------------------------------
__global__ __launch_bounds__(256) void prep_kernel(
    const float* __restrict__ q, const float* __restrict__ k,
    const float* __restrict__ v,
    const float* __restrict__ W0, const float* __restrict__ W1,
    const float* __restrict__ W2, const float* __restrict__ W3,
    const float* __restrict__ rpe,
    float* __restrict__ xt, float* __restrict__ wt)
{
    __shared__ float tile[32][33];
    const int z = blockIdx.z;

    if (z < 3) {
        const float* x = (z == 0) ? q : (z == 1) ? k : v;
        float* dst = xt + (size_t)z * S_LEN * D_MODEL;
        int i = (blockIdx.x * 256 + threadIdx.x) * 4;
        float4 vv = *(const float4*)(x + i);
        vv.x = tf32_round(vv.x); vv.y = tf32_round(vv.y);
        vv.z = tf32_round(vv.z); vv.w = tf32_round(vv.w);
        *(float4*)(dst + i) = vv;
    } else if (z == 3) {
        int wsel = blockIdx.x >> 10;
        int t2 = blockIdx.x & 1023;
        const float* W = (wsel == 0) ? W0 : (wsel == 1) ? W1 : (wsel == 2) ? W2 : W3;
        float* Wt = wt + (size_t)wsel * D_MODEL * D_MODEL;
        int n0 = (t2 & 31) * 32, k0 = (t2 >> 5) * 32;
        int tx = threadIdx.x & 31, ty = threadIdx.x >> 5;  // 32x8
#pragma unroll
        for (int j = 0; j < 4; j++)
            tile[ty + j * 8][tx] = W[(k0 + ty + j * 8) * D_MODEL + n0 + tx];
        __syncthreads();
#pragma unroll
        for (int j = 0; j < 4; j++) {
            float vv = tile[tx][ty + j * 8];
            int n = n0 + ty + j * 8, kk = k0 + tx;
            Wt[n * D_MODEL + kk] = tf32_round(vv);
        }
    } else {
        if (blockIdx.x >= 256) return;
        int idx = blockIdx.x * 256 + threadIdx.x;
        int h = idx / S_LEN;
        int n = idx % S_LEN;
        int bucket;
        if (n < 16) {
            bucket = n;
        } else {
            float t = logf((float)n * 0.0625f);
            float vv = t / 5.545177444479562f;
            vv = vv * 16.0f;
            bucket = 16 + (int)vv;
            if (bucket > NUM_BUCKETS - 1) bucket = NUM_BUCKETS - 1;
        }
        g_bias[h * S_LEN + n] = rpe[bucket * NUM_HEADS + h] * LOG2E;
    }
}

// ---------------------------------------------------------------------------
// Single-pass tf32 tensor-core GEMM (round-14 winner, unchanged).
// ---------------------------------------------------------------------------
#define GT_TILE 4608                   // 128*36 floats per tile
#define GT_BUF  (2 * GT_TILE)          // A + B per buffer
#define GSMEM_BYTES (2 * GT_BUF * 4)   // 73728 B

template <bool PROJ3>
__global__ __launch_bounds__(256, 2) void gemm_tf32(
    const float* __restrict__ Xb, const float* __restrict__ Wb,
    const float* __restrict__ b0p, const float* __restrict__ b1p,
    const float* __restrict__ b2p,
    float* __restrict__ Y0, float* __restrict__ Y1, float* __restrict__ Y2,
    float qscale)
{
    extern __shared__ float smem[];
    const int tid = threadIdx.x;
    const int lane = tid & 31, warp = tid >> 5;
    const int wm = warp & 1, wn = warp >> 1;
    const int g = lane >> 2, t = lane & 3;
    const int brow = blockIdx.y * 128, bcol = blockIdx.x * 128;

    const int z = PROJ3 ? blockIdx.z : 0;
    const float* X = Xb + (size_t)z * S_LEN * D_MODEL;
    const float* W = Wb + (size_t)z * D_MODEL * D_MODEL;
    const float* bias = (z == 0) ? b0p : (z == 1) ? b1p : b2p;
    float* Y = (z == 0) ? Y0 : (z == 1) ? Y1 : Y2;
    const float scale = (PROJ3 && z == 0) ? qscale : 1.0f;

    float acc[4][4][4];
#pragma unroll
    for (int a = 0; a < 4; a++)
#pragma unroll
        for (int b = 0; b < 4; b++)
#pragma unroll
            for (int c = 0; c < 4; c++) acc[a][b][c] = 0.f;

    uint32_t sbase = (uint32_t)__cvta_generic_to_shared(smem);

    const uint32_t laneA = (uint32_t)(((lane & 7) + ((lane >> 3) & 1) * 8) * 144
                                      + (lane >> 4) * 16);
    const uint32_t laneB = (uint32_t)(((lane & 7) + ((lane >> 4) << 3)) * 144
                                      + ((lane >> 3) & 1) * 16);

    auto load_tiles = [&](int buf, int kk) {
        const uint32_t bb = sbase + (uint32_t)(buf * GT_BUF) * 4;
#pragma unroll
        for (int i = 0; i < 4; i++) {
            int chunk = tid + i * 256;
            int row = chunk >> 3, off = chunk & 7;
            cpa16(bb + row * 144 + off * 16,
                  X + (size_t)(brow + row) * D_MODEL + kk + off * 4);
            cpa16(bb + (uint32_t)GT_TILE * 4 + row * 144 + off * 16,
                  W + (size_t)(bcol + row) * D_MODEL + kk + off * 4);
        }
    };

    load_tiles(0, 0);
    cpa_commit();

    for (int kt = 0; kt < 32; kt++) {
        int buf = kt & 1;
        if (kt + 1 < 32) {
            load_tiles(buf ^ 1, (kt + 1) * 32);
            cpa_commit();
            cpa_wait<1>();
        } else {
            cpa_wait<0>();
        }
        __syncthreads();

        const uint32_t bx = sbase + (uint32_t)(buf * GT_BUF) * 4;
        const uint32_t bw = bx + (uint32_t)GT_TILE * 4;

#pragma unroll
        for (int kc = 0; kc < 4; kc++) {
            const uint32_t kofs = (uint32_t)(kc * 32);
            unsigned bf0[4], bf1[4];
            ldsm4(bf0[0], bf0[1], bf0[2], bf0[3],
                  bw + laneB + (uint32_t)((wn * 32) * 144) + kofs);
            ldsm4(bf1[0], bf1[1], bf1[2], bf1[3],
                  bw + laneB + (uint32_t)((wn * 32 + 16) * 144) + kofs);
#pragma unroll
            for (int mt = 0; mt < 4; mt++) {
                unsigned a0, a1, a2, a3;
                ldsm4(a0, a1, a2, a3,
                      bx + laneA + (uint32_t)((wm * 64 + mt * 16) * 144) + kofs);
                mma_tf32(acc[mt][0], a0, a1, a2, a3, bf0[0], bf0[1]);
                mma_tf32(acc[mt][1], a0, a1, a2, a3, bf0[2], bf0[3]);
                mma_tf32(acc[mt][2], a0, a1, a2, a3, bf1[0], bf1[1]);
                mma_tf32(acc[mt][3], a0, a1, a2, a3, bf1[2], bf1[3]);
            }
        }
        __syncthreads();
    }

#pragma unroll
    for (int mt = 0; mt < 4; mt++) {
        int r0 = brow + wm * 64 + mt * 16 + g;
#pragma unroll
        for (int nt = 0; nt < 4; nt++) {
            int col = bcol + wn * 32 + nt * 8 + 2 * t;
            float bb0 = bias[col], bb1 = bias[col + 1];
            float v00 = acc[mt][nt][0] + bb0, v01 = acc[mt][nt][1] + bb1;
            float v10 = acc[mt][nt][2] + bb0, v11 = acc[mt][nt][3] + bb1;
            if (PROJ3) {
                int head = col >> 6, cc = col & 63;
                float* p0 = Y + (size_t)head * S_LEN * DK + (size_t)r0 * DK + cc;
                float* p1 = Y + (size_t)head * S_LEN * DK + (size_t)(r0 + 8) * DK + cc;
                *(float2*)p0 = make_float2(tf32_round(v00 * scale), tf32_round(v01 * scale));
                *(float2*)p1 = make_float2(tf32_round(v10 * scale), tf32_round(v11 * scale));
            } else {
                *(float2*)(Y + (size_t)r0 * D_MODEL + col) = make_float2(v00, v01);
                *(float2*)(Y + (size_t)(r0 + 8) * D_MODEL + col) = make_float2(v10, v11);
            }
        }
    }
}

// ---------------------------------------------------------------------------
// Flash attention v5: 128-key load tiles (double buffered) with TWO 64-column
// compute halves each -> barriers/load overhead halved per key, numerics
// identical to the 64-key version. Transposed grid (global big-first order),
// q-tile 128 (8 warps x 16 rows), tf32 MMA, exp2-domain softmax.
// ---------------------------------------------------------------------------
#define F_KROW 68
#define F_VROW 72
#define F_KBUF (128 * F_KROW)            // 8704 floats
#define F_VBUF (128 * F_VROW)            // 9216
#define F_KS 0
#define F_VS (2 * F_KBUF)                // 17408
#define F_PS (F_VS + 2 * F_VBUF)         // 35840
#define F_SB (F_PS + 128 * 68)           // 44544
#define F_SBUF 256
#define F_FLOATS (F_SB + 2 * F_SBUF)     // 45056 floats = 180224 B

__global__ __launch_bounds__(256) void flash_mma_kernel(float* __restrict__ ctx)
{
    extern __shared__ float sm[];
    const int h = blockIdx.x;
    const int qt = 31 - (int)blockIdx.y;   // biggest tiles first, all heads
    const int qbase = qt * 128;
    const int tid = threadIdx.x;
    const int lane = tid & 31, w = tid >> 5;
    const int g = lane >> 2, t = lane & 3;
    const int wrow = w * 16;
    const int r0 = wrow + g, r1 = r0 + 8;

    const float* Qg = g_Q + ((size_t)h * S_LEN + qbase + wrow) * DK;
    const float* Kg = g_K + (size_t)h * S_LEN * DK;
    const float* Vg = g_V + (size_t)h * S_LEN * DK;
    const float* Bg = g_bias + h * S_LEN;

    uint32_t sb32 = (uint32_t)__cvta_generic_to_shared(sm);

    // load 128 keys (K+V) + bias window into buffer b
    auto load_tile = [&](int b, int kt128) {
        const int kb = kt128 * 128;
        const float4* K4 = (const float4*)(Kg + (size_t)kb * DK);
        const float4* V4 = (const float4*)(Vg + (size_t)kb * DK);
#pragma unroll
        for (int i = 0; i < 8; i++) {
            int idx = tid + i * 256;           // 0..2047
            int key = idx >> 4, d4 = idx & 15;
            cpa16(sb32 + (uint32_t)(F_KS + b * F_KBUF + key * F_KROW + d4 * 4) * 4,
                  K4 + idx);
            cpa16(sb32 + (uint32_t)(F_VS + b * F_VBUF + key * F_VROW + d4 * 4) * 4,
                  V4 + idx);
        }
        // bias window: Sb[i] = bias[d0 - 127 + i], i in [0,256)
        int d0 = qbase - kb;
        int delta = d0 - 127 + tid;
        if (delta >= 0 && delta < S_LEN) {
            cpa4(sb32 + (uint32_t)(F_SB + b * F_SBUF + tid) * 4, Bg + delta);
        } else {
            sm[F_SB + b * F_SBUF + tid] = 0.f;
        }
    };

    unsigned qa[8][4];
#pragma unroll
    for (int kc = 0; kc < 8; kc++) {
        qa[kc][0] = __float_as_uint(Qg[g       * DK + kc * 8 + t]);
        qa[kc][1] = __float_as_uint(Qg[(g + 8) * DK + kc * 8 + t]);
        qa[kc][2] = __float_as_uint(Qg[g       * DK + kc * 8 + t + 4]);
        qa[kc][3] = __float_as_uint(Qg[(g + 8) * DK + kc * 8 + t + 4]);
    }

    float O[8][4];
#pragma unroll
    for (int db = 0; db < 8; db++)
#pragma unroll
        for (int c = 0; c < 4; c++) O[db][c] = 0.f;
    float m0 = -INFINITY, m1 = -INFINITY, l0 = 0.f, l1 = 0.f;

    const int nt128 = qt + 1;              // number of 128-key tiles
    load_tile(0, 0);
    cpa_commit();

    for (int kt = 0; kt < nt128; kt++) {
        const int buf = kt & 1;
        if (kt + 1 < nt128) {
            load_tile(buf ^ 1, kt + 1);
            cpa_commit();
            cpa_wait<1>();
        } else {
            cpa_wait<0>();
        }
        __syncthreads();

        const float* Sb = sm + F_SB + buf * F_SBUF;
        float* Pw = sm + F_PS + wrow * 68;

#pragma unroll
        for (int hh = 0; hh < 2; hh++) {
            const int kbase = kt * 128 + hh * 64;
            const int d0 = qbase - kbase;
            if (kbase > qbase + wrow + 15) continue;

            const float* Ks = sm + F_KS + buf * F_KBUF + hh * 64 * F_KROW;
            const float* Vs = sm + F_VS + buf * F_VBUF + hh * 64 * F_VROW;
            const int sbofs = 127 - hh * 64;   // Sb[r - col + sbofs]

            float Sc[8][4];
#pragma unroll
            for (int nb = 0; nb < 8; nb++)
#pragma unroll
                for (int c = 0; c < 4; c++) Sc[nb][c] = 0.f;
#pragma unroll
            for (int kc = 0; kc < 8; kc++) {
#pragma unroll
                for (int nb = 0; nb < 8; nb++) {
                    unsigned b0 = __float_as_uint(Ks[(nb * 8 + g) * F_KROW + kc * 8 + t]);
                    unsigned b1 = __float_as_uint(Ks[(nb * 8 + g) * F_KROW + kc * 8 + t + 4]);
                    mma_tf32(Sc[nb], qa[kc][0], qa[kc][1], qa[kc][2], qa[kc][3], b0, b1);
                }
            }

            float mt0 = -INFINITY, mt1 = -INFINITY;
#pragma unroll
            for (int nb = 0; nb < 8; nb++) {
                int col0 = nb * 8 + 2 * t + hh * 64;   // absolute col within 128-tile
                int c64 = nb * 8 + 2 * t;
                float v00 = Sc[nb][0] + Sb[r0 - c64 + sbofs];
                float v01 = Sc[nb][1] + Sb[r0 - c64 + sbofs - 1];
                float v10 = Sc[nb][2] + Sb[r1 - c64 + sbofs];
                float v11 = Sc[nb][3] + Sb[r1 - c64 + sbofs - 1];
                Sc[nb][0] = (d0 + r0 - c64     >= 0) ? v00 : -1e30f;
                Sc[nb][1] = (d0 + r0 - c64 - 1 >= 0) ? v01 : -1e30f;
                Sc[nb][2] = (d0 + r1 - c64     >= 0) ? v10 : -1e30f;
                Sc[nb][3] = (d0 + r1 - c64 - 1 >= 0) ? v11 : -1e30f;
                mt0 = fmaxf(mt0, fmaxf(Sc[nb][0], Sc[nb][1]));
                mt1 = fmaxf(mt1, fmaxf(Sc[nb][2], Sc[nb][3]));
                (void)col0;
            }
            mt0 = fmaxf(mt0, __shfl_xor_sync(0xffffffffu, mt0, 1));
            mt0 = fmaxf(mt0, __shfl_xor_sync(0xffffffffu, mt0, 2));
            mt1 = fmaxf(mt1, __shfl_xor_sync(0xffffffffu, mt1, 1));
            mt1 = fmaxf(mt1, __shfl_xor_sync(0xffffffffu, mt1, 2));

            float mn0 = fmaxf(m0, mt0), mn1 = fmaxf(m1, mt1);
            float corr0 = exp2f(m0 - mn0), corr1 = exp2f(m1 - mn1);
            float ls0 = 0.f, ls1 = 0.f;
#pragma unroll
            for (int nb = 0; nb < 8; nb++) {
                Sc[nb][0] = exp2f(Sc[nb][0] - mn0);
                Sc[nb][1] = exp2f(Sc[nb][1] - mn0);
                Sc[nb][2] = exp2f(Sc[nb][2] - mn1);
                Sc[nb][3] = exp2f(Sc[nb][3] - mn1);
                ls0 += Sc[nb][0] + Sc[nb][1];
                ls1 += Sc[nb][2] + Sc[nb][3];
            }
            ls0 += __shfl_xor_sync(0xffffffffu, ls0, 1);
            ls0 += __shfl_xor_sync(0xffffffffu, ls0, 2);
            ls1 += __shfl_xor_sync(0xffffffffu, ls1, 1);
            ls1 += __shfl_xor_sync(0xffffffffu, ls1, 2);
            l0 = l0 * corr0 + ls0;  m0 = mn0;
            l1 = l1 * corr1 + ls1;  m1 = mn1;

#pragma unroll
            for (int db = 0; db < 8; db++) {
                O[db][0] *= corr0; O[db][1] *= corr0;
                O[db][2] *= corr1; O[db][3] *= corr1;
            }

#pragma unroll
            for (int nb = 0; nb < 8; nb++) {
                int c64 = nb * 8 + 2 * t;
                *(float2*)&Pw[g * 68 + c64] = make_float2(Sc[nb][0], Sc[nb][1]);
                *(float2*)&Pw[(g + 8) * 68 + c64] = make_float2(Sc[nb][2], Sc[nb][3]);
            }
            __syncwarp();

#pragma unroll
            for (int kc2 = 0; kc2 < 8; kc2++) {
                unsigned pa0 = __float_as_uint(Pw[g       * 68 + kc2 * 8 + t]);
                unsigned pa1 = __float_as_uint(Pw[(g + 8) * 68 + kc2 * 8 + t]);
                unsigned pa2 = __float_as_uint(Pw[g       * 68 + kc2 * 8 + t + 4]);
                unsigned pa3 = __float_as_uint(Pw[(g + 8) * 68 + kc2 * 8 + t + 4]);
#pragma unroll
                for (int db = 0; db < 8; db++) {
                    unsigned vb0 = __float_as_uint(Vs[(kc2 * 8 + t)     * F_VROW + db * 8 + g]);
                    unsigned vb1 = __float_as_uint(Vs[(kc2 * 8 + t + 4) * F_VROW + db * 8 + g]);
                    mma_tf32(O[db], pa0, pa1, pa2, pa3, vb0, vb1);
                }
            }
            __syncwarp();
        }
        __syncthreads();
    }

    // normalize + tf32-rounded fp32 ctx write
    float inv0 = 1.f / l0, inv1 = 1.f / l1;
    float* dst0 = ctx + (size_t)(qbase + r0) * D_MODEL + h * DK;
    float* dst1 = ctx + (size_t)(qbase + r1) * D_MODEL + h * DK;
#pragma unroll
    for (int db = 0; db < 8; db++) {
        int col = db * 8 + 2 * t;
        *(float2*)(dst0 + col) = make_float2(tf32_round(O[db][0] * inv0),
                                             tf32_round(O[db][1] * inv0));
        *(float2*)(dst1 + col) = make_float2(tf32_round(O[db][2] * inv1),
                                             tf32_round(O[db][3] * inv1));
    }
}

// ---------------------------------------------------------------------------
extern "C" void kernel_launch(void* const* d_in, const int* in_sizes, int n_in,
                              void* d_out, int out_size)
{
    const float* query = (const float*)d_in[0];
    const float* key   = (const float*)d_in[1];
    const float* value = (const float*)d_in[2];
    const float* Wq = (const float*)d_in[4];
    const float* bq = (const float*)d_in[5];
    const float* Wk = (const float*)d_in[6];
    const float* bk = (const float*)d_in[7];
    const float* Wv = (const float*)d_in[8];
    const float* bv = (const float*)d_in[9];
    const float* Wo = (const float*)d_in[10];
    const float* bo = (const float*)d_in[11];
    const float* rpe = (const float*)d_in[12];
    float* out = (float*)d_out;

    float *gQ, *gK, *gV, *xt, *wt, *ct;
    cudaGetSymbolAddress((void**)&gQ, g_Q);
    cudaGetSymbolAddress((void**)&gK, g_K);
    cudaGetSymbolAddress((void**)&gV, g_V);
    cudaGetSymbolAddress((void**)&xt, g_XT);
    cudaGetSymbolAddress((void**)&wt, g_WT);
    cudaGetSymbolAddress((void**)&ct, g_CT);

    const int WN = D_MODEL * D_MODEL;

    // fused prep: tf32 rounding of inputs + weight transposes + bias table
    dim3 prep_grid(4096, 1, 5);
    prep_kernel<<<prep_grid, 256>>>(query, key, value, Wq, Wk, Wv, Wo, rpe, xt, wt);

    cudaFuncSetAttribute(gemm_tf32<true>,
                         cudaFuncAttributeMaxDynamicSharedMemorySize, GSMEM_BYTES);
    cudaFuncSetAttribute(gemm_tf32<false>,
                         cudaFuncAttributeMaxDynamicSharedMemorySize, GSMEM_BYTES);

    // fused Q/K/V projections (one launch, grid.z = matrix)
    dim3 pgrid(D_MODEL / 128, S_LEN / 128, 3);
    const float qscale = 0.125f * LOG2E;
    gemm_tf32<true><<<pgrid, 256, GSMEM_BYTES>>>(
        xt, wt, bq, bk, bv, gQ, gK, gV, qscale);

    size_t fsmem = F_FLOATS * sizeof(float);
    cudaFuncSetAttribute(flash_mma_kernel, cudaFuncAttributeMaxDynamicSharedMemorySize,
                         (int)fsmem);
    dim3 fgrid(NUM_HEADS, S_LEN / 128);   // head-fastest: global big-first order
    flash_mma_kernel<<<fgrid, 256, fsmem>>>(ct);

    // output projection
    dim3 ogrid(D_MODEL / 128, S_LEN / 128, 1);
    gemm_tf32<false><<<ogrid, 256, GSMEM_BYTES>>>(
        ct, wt + 3 * WN, bo, bo, bo, out, out, out, 1.0f);
    (void)in_sizes; (void)n_in; (void)out_size;
}

// round 16
// speedup vs baseline: 1.0673x; 1.0673x over previous
#include <cuda_runtime.h>
#include <cuda_bf16.h>
#include <math.h>
#include <stdint.h>
#include <cstdint>

// Problem constants
#define S_LEN 4096
#define D_MODEL 1024
#define NUM_HEADS 16
#define DK 64
#define NUM_BUCKETS 32
#define LOG2E 1.4426950408889634f

// Scratch (device globals: no allocation allowed)
__device__ float g_Q[NUM_HEADS * S_LEN * DK];
__device__ float g_K[NUM_HEADS * S_LEN * DK];
__device__ float g_V[NUM_HEADS * S_LEN * DK];
__device__ float g_bias[NUM_HEADS * S_LEN];

// tf32-rounded fp32 operands
__device__ float g_XT[3 * S_LEN * D_MODEL];        // rounded inputs q/k/v
__device__ float g_WT[4 * D_MODEL * D_MODEL];      // transposed rounded weights [n][k]
__device__ float g_CT[S_LEN * D_MODEL];            // rounded attention context

// ---------------------------------------------------------------------------
// helpers
// ---------------------------------------------------------------------------
__device__ __forceinline__ float tf32_round(float x) {
    unsigned u;
    asm("cvt.rna.tf32.f32 %0, %1;" : "=r"(u) : "f"(x));
    return __uint_as_float(u);
}

__device__ __forceinline__ void mma_tf32(float c[4],
                                         unsigned a0, unsigned a1, unsigned a2, unsigned a3,
                                         unsigned b0, unsigned b1) {
    asm volatile(
        "mma.sync.aligned.m16n8k8.row.col.f32.tf32.tf32.f32 "
        "{%0,%1,%2,%3}, {%4,%5,%6,%7}, {%8,%9}, {%0,%1,%2,%3};"
        : "+f"(c[0]), "+f"(c[1]), "+f"(c[2]), "+f"(c[3])
        : "r"(a0), "r"(a1), "r"(a2), "r"(a3), "r"(b0), "r"(b1));
}

__device__ __forceinline__ void ldsm4(unsigned &r0, unsigned &r1, unsigned &r2,
                                      unsigned &r3, uint32_t addr) {
    asm volatile("ldmatrix.sync.aligned.m8n8.x4.shared.b16 {%0,%1,%2,%3}, [%4];"
                 : "=r"(r0), "=r"(r1), "=r"(r2), "=r"(r3) : "r"(addr));
}

__device__ __forceinline__ void cpa16(uint32_t saddr, const void* g) {
    asm volatile("cp.async.cg.shared.global [%0], [%1], 16;" :: "r"(saddr), "l"(g));
}
__device__ __forceinline__ void cpa4(uint32_t saddr, const void* g) {
    asm volatile("cp.async.ca.shared.global [%0], [%1], 4;" :: "r"(saddr), "l"(g));
}
__device__ __forceinline__ void cpa_commit() {
    asm volatile("cp.async.commit_group;");
}
template <int N>
__device__ __forceinline__ void cpa_wait() {
    asm volatile("cp.async.wait_group %0;" :: "n"(N));
}

// ---------------------------------------------------------------------------
// Fused prep kernel: grid.z selects the job.
//  z=0..2 : tf32-round inputs (query/key/value) into g_XT, 4096 blocks
//  z=3    : all 4 weight transposes (tf32-rounded), 4096 blocks
//  z=4    : bias table (256 blocks used)
// ---------------------------------------------------------------------------
__global__ __launch_bounds__(256) void prep_kernel(
    const float* __restrict__ q, const float* __restrict__ k,
    const float* __restrict__ v,
    const float* __restrict__ W0, const float* __restrict__ W1,
    const float* __restrict__ W2, const float* __restrict__ W3,
    const float* __restrict__ rpe,
    float* __restrict__ xt, float* __restrict__ wt)
{
    __shared__ float tile[32][33];
    const int z = blockIdx.z;

    if (z < 3) {
        const float* x = (z == 0) ? q : (z == 1) ? k : v;
        float* dst = xt + (size_t)z * S_LEN * D_MODEL;
        int i = (blockIdx.x * 256 + threadIdx.x) * 4;
        float4 vv = *(const float4*)(x + i);
        vv.x = tf32_round(vv.x); vv.y = tf32_round(vv.y);
        vv.z = tf32_round(vv.z); vv.w = tf32_round(vv.w);
        *(float4*)(dst + i) = vv;
    } else if (z == 3) {
        int wsel = blockIdx.x >> 10;
        int t2 = blockIdx.x & 1023;
        const float* W = (wsel == 0) ? W0 : (wsel == 1) ? W1 : (wsel == 2) ? W2 : W3;
        float* Wt = wt + (size_t)wsel * D_MODEL * D_MODEL;
        int n0 = (t2 & 31) * 32, k0 = (t2 >> 5) * 32;
        int tx = threadIdx.x & 31, ty = threadIdx.x >> 5;  // 32x8
#pragma unroll
        for (int j = 0; j < 4; j++)
            tile[ty + j * 8][tx] = W[(k0 + ty + j * 8) * D_MODEL + n0 + tx];
        __syncthreads();
#pragma unroll
        for (int j = 0; j < 4; j++) {
            float vv = tile[tx][ty + j * 8];
            int n = n0 + ty + j * 8, kk = k0 + tx;
            Wt[n * D_MODEL + kk] = tf32_round(vv);
        }
    } else {
        if (blockIdx.x >= 256) return;
        int idx = blockIdx.x * 256 + threadIdx.x;
        int h = idx / S_LEN;
        int n = idx % S_LEN;
        int bucket;
        if (n < 16) {
            bucket = n;
        } else {
            float t = logf((float)n * 0.0625f);
            float vv = t / 5.545177444479562f;
            vv = vv * 16.0f;
            bucket = 16 + (int)vv;
            if (bucket > NUM_BUCKETS - 1) bucket = NUM_BUCKETS - 1;
        }
        g_bias[h * S_LEN + n] = rpe[bucket * NUM_HEADS + h] * LOG2E;
    }
}

// ---------------------------------------------------------------------------
// Single-pass tf32 tensor-core GEMM: Y[4096,1024] = X @ W + b
// X tf32-rounded row-major; W tf32-rounded transposed [n][k].
// Block tile 128x128, BK=32, 256 threads = 8 warps (2m x 4n), warp tile 64x32.
// fp32 smem tiles, rows padded to 36 floats (144B -> conflict-free ldmatrix).
// Fragments loaded with ldmatrix.b16 treating fp32 as 4-byte pairs.
// ---------------------------------------------------------------------------
#define GT_TILE 4608                   // 128*36 floats per tile
#define GT_BUF  (2 * GT_TILE)          // A + B per buffer
#define GSMEM_BYTES (2 * GT_BUF * 4)   // 73728 B

template <bool PROJ3>
__global__ __launch_bounds__(256, 2) void gemm_tf32(
    const float* __restrict__ Xb, const float* __restrict__ Wb,
    const float* __restrict__ b0p, const float* __restrict__ b1p,
    const float* __restrict__ b2p,
    float* __restrict__ Y0, float* __restrict__ Y1, float* __restrict__ Y2,
    float qscale)
{
    extern __shared__ float smem[];
    const int tid = threadIdx.x;
    const int lane = tid & 31, warp = tid >> 5;
    const int wm = warp & 1, wn = warp >> 1;
    const int g = lane >> 2, t = lane & 3;
    const int brow = blockIdx.y * 128, bcol = blockIdx.x * 128;

    const int z = PROJ3 ? blockIdx.z : 0;
    const float* X = Xb + (size_t)z * S_LEN * D_MODEL;
    const float* W = Wb + (size_t)z * D_MODEL * D_MODEL;
    const float* bias = (z == 0) ? b0p : (z == 1) ? b1p : b2p;
    float* Y = (z == 0) ? Y0 : (z == 1) ? Y1 : Y2;
    const float scale = (PROJ3 && z == 0) ? qscale : 1.0f;

    float acc[4][4][4];
#pragma unroll
    for (int a = 0; a < 4; a++)
#pragma unroll
        for (int b = 0; b < 4; b++)
#pragma unroll
            for (int c = 0; c < 4; c++) acc[a][b][c] = 0.f;

    uint32_t sbase = (uint32_t)__cvta_generic_to_shared(smem);

    // ldmatrix lane byte-offsets (tf32-as-b16 trick), 144B row stride
    const uint32_t laneA = (uint32_t)(((lane & 7) + ((lane >> 3) & 1) * 8) * 144
                                      + (lane >> 4) * 16);
    const uint32_t laneB = (uint32_t)(((lane & 7) + ((lane >> 4) << 3)) * 144
                                      + ((lane >> 3) & 1) * 16);

    auto load_tiles = [&](int buf, int kk) {
        const uint32_t bb = sbase + (uint32_t)(buf * GT_BUF) * 4;
#pragma unroll
        for (int i = 0; i < 4; i++) {
            int chunk = tid + i * 256;           // 0..1023
            int row = chunk >> 3, off = chunk & 7;
            cpa16(bb + row * 144 + off * 16,
                  X + (size_t)(brow + row) * D_MODEL + kk + off * 4);
            cpa16(bb + (uint32_t)GT_TILE * 4 + row * 144 + off * 16,
                  W + (size_t)(bcol + row) * D_MODEL + kk + off * 4);
        }
    };

    load_tiles(0, 0);
    cpa_commit();

    for (int kt = 0; kt < 32; kt++) {
        int buf = kt & 1;
        if (kt + 1 < 32) {
            load_tiles(buf ^ 1, (kt + 1) * 32);
            cpa_commit();
            cpa_wait<1>();
        } else {
            cpa_wait<0>();
        }
        __syncthreads();

        const uint32_t bx = sbase + (uint32_t)(buf * GT_BUF) * 4;
        const uint32_t bw = bx + (uint32_t)GT_TILE * 4;

#pragma unroll
        for (int kc = 0; kc < 4; kc++) {
            const uint32_t kofs = (uint32_t)(kc * 32);    // 8 fp32 = 32B
            unsigned bf0[4], bf1[4];
            ldsm4(bf0[0], bf0[1], bf0[2], bf0[3],
                  bw + laneB + (uint32_t)((wn * 32) * 144) + kofs);
            ldsm4(bf1[0], bf1[1], bf1[2], bf1[3],
                  bw + laneB + (uint32_t)((wn * 32 + 16) * 144) + kofs);
#pragma unroll
            for (int mt = 0; mt < 4; mt++) {
                unsigned a0, a1, a2, a3;
                ldsm4(a0, a1, a2, a3,
                      bx + laneA + (uint32_t)((wm * 64 + mt * 16) * 144) + kofs);
                mma_tf32(acc[mt][0], a0, a1, a2, a3, bf0[0], bf0[1]);
                mma_tf32(acc[mt][1], a0, a1, a2, a3, bf0[2], bf0[3]);
                mma_tf32(acc[mt][2], a0, a1, a2, a3, bf1[0], bf1[1]);
                mma_tf32(acc[mt][3], a0, a1, a2, a3, bf1[2], bf1[3]);
            }
        }
        __syncthreads();
    }

    // epilogue
#pragma unroll
    for (int mt = 0; mt < 4; mt++) {
        int r0 = brow + wm * 64 + mt * 16 + g;
#pragma unroll
        for (int nt = 0; nt < 4; nt++) {
            int col = bcol + wn * 32 + nt * 8 + 2 * t;
            float bb0 = bias[col], bb1 = bias[col + 1];
            float v00 = acc[mt][nt][0] + bb0, v01 = acc[mt][nt][1] + bb1;
            float v10 = acc[mt][nt][2] + bb0, v11 = acc[mt][nt][3] + bb1;
            if (PROJ3) {
                int head = col >> 6, cc = col & 63;
                float* p0 = Y + (size_t)head * S_LEN * DK + (size_t)r0 * DK + cc;
                float* p1 = Y + (size_t)head * S_LEN * DK + (size_t)(r0 + 8) * DK + cc;
                *(float2*)p0 = make_float2(tf32_round(v00 * scale), tf32_round(v01 * scale));
                *(float2*)p1 = make_float2(tf32_round(v10 * scale), tf32_round(v11 * scale));
            } else {
                *(float2*)(Y + (size_t)r0 * D_MODEL + col) = make_float2(v00, v01);
                *(float2*)(Y + (size_t)(r0 + 8) * D_MODEL + col) = make_float2(v10, v11);
            }
        }
    }
}

// ---------------------------------------------------------------------------
// Flash attention (round-14 winner): transposed grid (head fastest -> global
// big-tiles-first schedule), q-tile 128, k-tile 64, double-buffered cp.async,
// tf32 MMA, exp2-domain softmax. Epilogue writes tf32-rounded fp32 ctx.
// ---------------------------------------------------------------------------
#define F_KS 0
#define F_KBUF 4352                  // 64*68
#define F_VS (2 * F_KBUF)            // 8704
#define F_VBUF 4608                  // 64*72
#define F_PS (F_VS + 2 * F_VBUF)     // 17920
#define F_SB (F_PS + 128 * 68)       // 26624
#define F_SBUF 192
#define F_FLOATS (F_SB + 2 * F_SBUF) // 27008 floats = 108032 B

__global__ __launch_bounds__(256) void flash_mma_kernel(float* __restrict__ ctx)
{
    extern __shared__ float sm[];
    const int h = blockIdx.x;
    const int qt = 31 - (int)blockIdx.y;   // biggest tiles first, all heads
    const int qbase = qt * 128;
    const int tid = threadIdx.x;
    const int lane = tid & 31, w = tid >> 5;
    const int g = lane >> 2, t = lane & 3;
    const int wrow = w * 16;
    const int r0 = wrow + g, r1 = r0 + 8;

    const float* Qg = g_Q + ((size_t)h * S_LEN + qbase + wrow) * DK;
    const float* Kg = g_K + (size_t)h * S_LEN * DK;
    const float* Vg = g_V + (size_t)h * S_LEN * DK;
    const float* Bg = g_bias + h * S_LEN;

    uint32_t sb32 = (uint32_t)__cvta_generic_to_shared(sm);

    auto load_tile = [&](int b, int kt2) {
        const int kb = kt2 * 64;
        const float4* K4 = (const float4*)(Kg + (size_t)kb * DK);
        const float4* V4 = (const float4*)(Vg + (size_t)kb * DK);
#pragma unroll
        for (int i = 0; i < 4; i++) {
            int idx = tid + i * 256;
            int key = idx >> 4, d4 = idx & 15;
            cpa16(sb32 + (uint32_t)(F_KS + b * F_KBUF + key * 68 + d4 * 4) * 4, K4 + idx);
            cpa16(sb32 + (uint32_t)(F_VS + b * F_VBUF + key * 72 + d4 * 4) * 4, V4 + idx);
        }
        int dd0 = qbase - kb;
        if (tid < 191) {
            if (dd0 >= 63) {
                cpa4(sb32 + (uint32_t)(F_SB + b * F_SBUF + tid) * 4, Bg + dd0 - 63 + tid);
            } else {
                int delta = dd0 - 63 + tid;
                sm[F_SB + b * F_SBUF + tid] = (delta >= 0) ? Bg[delta] : 0.f;
            }
        }
    };

    unsigned qa[8][4];
#pragma unroll
    for (int kc = 0; kc < 8; kc++) {
        qa[kc][0] = __float_as_uint(Qg[g       * DK + kc * 8 + t]);
        qa[kc][1] = __float_as_uint(Qg[(g + 8) * DK + kc * 8 + t]);
        qa[kc][2] = __float_as_uint(Qg[g       * DK + kc * 8 + t + 4]);
        qa[kc][3] = __float_as_uint(Qg[(g + 8) * DK + kc * 8 + t + 4]);
    }

    float O[8][4];
#pragma unroll
    for (int db = 0; db < 8; db++)
#pragma unroll
        for (int c = 0; c < 4; c++) O[db][c] = 0.f;
    float m0 = -INFINITY, m1 = -INFINITY, l0 = 0.f, l1 = 0.f;

    const int ktmax = 2 * qt + 1;
    load_tile(0, 0);
    cpa_commit();

    for (int kt = 0; kt <= ktmax; kt++) {
        const int buf = kt & 1;
        if (kt < ktmax) {
            load_tile(buf ^ 1, kt + 1);
            cpa_commit();
            cpa_wait<1>();
        } else {
            cpa_wait<0>();
        }
        __syncthreads();

        const int kbase = kt * 64;
        const int d0 = qbase - kbase;

        if (kbase <= qbase + wrow + 15) {
            const float* Ks = sm + F_KS + buf * F_KBUF;
            const float* Vs = sm + F_VS + buf * F_VBUF;
            const float* Sb = sm + F_SB + buf * F_SBUF;
            float* Pw = sm + F_PS + wrow * 68;

            float Sc[8][4];
#pragma unroll
            for (int nb = 0; nb < 8; nb++)
#pragma unroll
                for (int c = 0; c < 4; c++) Sc[nb][c] = 0.f;
#pragma unroll
            for (int kc = 0; kc < 8; kc++) {
#pragma unroll
                for (int nb = 0; nb < 8; nb++) {
                    unsigned b0 = __float_as_uint(Ks[(nb * 8 + g) * 68 + kc * 8 + t]);
                    unsigned b1 = __float_as_uint(Ks[(nb * 8 + g) * 68 + kc * 8 + t + 4]);
                    mma_tf32(Sc[nb], qa[kc][0], qa[kc][1], qa[kc][2], qa[kc][3], b0, b1);
                }
            }

            float mt0 = -INFINITY, mt1 = -INFINITY;
#pragma unroll
            for (int nb = 0; nb < 8; nb++) {
                int col0 = nb * 8 + 2 * t;
                float v00 = Sc[nb][0] + Sb[r0 - col0 + 63];
                float v01 = Sc[nb][1] + Sb[r0 - col0 + 62];
                float v10 = Sc[nb][2] + Sb[r1 - col0 + 63];
                float v11 = Sc[nb][3] + Sb[r1 - col0 + 62];
                Sc[nb][0] = (d0 + r0 - col0     >= 0) ? v00 : -1e30f;
                Sc[nb][1] = (d0 + r0 - col0 - 1 >= 0) ? v01 : -1e30f;
                Sc[nb][2] = (d0 + r1 - col0     >= 0) ? v10 : -1e30f;
                Sc[nb][3] = (d0 + r1 - col0 - 1 >= 0) ? v11 : -1e30f;
                mt0 = fmaxf(mt0, fmaxf(Sc[nb][0], Sc[nb][1]));
                mt1 = fmaxf(mt1, fmaxf(Sc[nb][2], Sc[nb][3]));
            }
            mt0 = fmaxf(mt0, __shfl_xor_sync(0xffffffffu, mt0, 1));
            mt0 = fmaxf(mt0, __shfl_xor_sync(0xffffffffu, mt0, 2));
            mt1 = fmaxf(mt1, __shfl_xor_sync(0xffffffffu, mt1, 1));
            mt1 = fmaxf(mt1, __shfl_xor_sync(0xffffffffu, mt1, 2));

            float mn0 = fmaxf(m0, mt0), mn1 = fmaxf(m1, mt1);
            float corr0 = exp2f(m0 - mn0), corr1 = exp2f(m1 - mn1);
            float ls0 = 0.f, ls1 = 0.f;
#pragma unroll
            for (int nb = 0; nb < 8; nb++) {
                Sc[nb][0] = exp2f(Sc[nb][0] - mn0);
                Sc[nb][1] = exp2f(Sc[nb][1] - mn0);
                Sc[nb][2] = exp2f(Sc[nb][2] - mn1);
                Sc[nb][3] = exp2f(Sc[nb][3] - mn1);
                ls0 += Sc[nb][0] + Sc[nb][1];
                ls1 += Sc[nb][2] + Sc[nb][3];
            }
            ls0 += __shfl_xor_sync(0xffffffffu, ls0, 1);
            ls0 += __shfl_xor_sync(0xffffffffu, ls0, 2);
            ls1 += __shfl_xor_sync(0xffffffffu, ls1, 1);
            ls1 += __shfl_xor_sync(0xffffffffu, ls1, 2);
            l0 = l0 * corr0 + ls0;  m0 = mn0;
            l1 = l1 * corr1 + ls1;  m1 = mn1;

#pragma unroll
            for (int db = 0; db < 8; db++) {
                O[db][0] *= corr0; O[db][1] *= corr0;
                O[db][2] *= corr1; O[db][3] *= corr1;
            }

#pragma unroll
            for (int nb = 0; nb < 8; nb++) {
                int col0 = nb * 8 + 2 * t;
                *(float2*)&Pw[g * 68 + col0] = make_float2(Sc[nb][0], Sc[nb][1]);
                *(float2*)&Pw[(g + 8) * 68 + col0] = make_float2(Sc[nb][2], Sc[nb][3]);
            }
            __syncwarp();

#pragma unroll
            for (int kc2 = 0; kc2 < 8; kc2++) {
                unsigned pa0 = __float_as_uint(Pw[g       * 68 + kc2 * 8 + t]);
                unsigned pa1 = __float_as_uint(Pw[(g + 8) * 68 + kc2 * 8 + t]);
                unsigned pa2 = __float_as_uint(Pw[g       * 68 + kc2 * 8 + t + 4]);
                unsigned pa3 = __float_as_uint(Pw[(g + 8) * 68 + kc2 * 8 + t + 4]);
#pragma unroll
                for (int db = 0; db < 8; db++) {
                    unsigned vb0 = __float_as_uint(Vs[(kc2 * 8 + t)     * 72 + db * 8 + g]);
                    unsigned vb1 = __float_as_uint(Vs[(kc2 * 8 + t + 4) * 72 + db * 8 + g]);
                    mma_tf32(O[db], pa0, pa1, pa2, pa3, vb0, vb1);
                }
            }
        }
        __syncthreads();
    }

    // normalize + tf32-rounded fp32 ctx write
    float inv0 = 1.f / l0, inv1 = 1.f / l1;
    float* dst0 = ctx + (size_t)(qbase + r0) * D_MODEL + h * DK;
    float* dst1 = ctx + (size_t)(qbase + r1) * D_MODEL + h * DK;
#pragma unroll
    for (int db = 0; db < 8; db++) {
        int col = db * 8 + 2 * t;
        *(float2*)(dst0 + col) = make_float2(tf32_round(O[db][0] * inv0),
                                             tf32_round(O[db][1] * inv0));
        *(float2*)(dst1 + col) = make_float2(tf32_round(O[db][2] * inv1),
                                             tf32_round(O[db][3] * inv1));
    }
}

// ---------------------------------------------------------------------------
extern "C" void kernel_launch(void* const* d_in, const int* in_sizes, int n_in,
                              void* d_out, int out_size)
{
    const float* query = (const float*)d_in[0];
    const float* key   = (const float*)d_in[1];
    const float* value = (const float*)d_in[2];
    const float* Wq = (const float*)d_in[4];
    const float* bq = (const float*)d_in[5];
    const float* Wk = (const float*)d_in[6];
    const float* bk = (const float*)d_in[7];
    const float* Wv = (const float*)d_in[8];
    const float* bv = (const float*)d_in[9];
    const float* Wo = (const float*)d_in[10];
    const float* bo = (const float*)d_in[11];
    const float* rpe = (const float*)d_in[12];
    float* out = (float*)d_out;

    float *gQ, *gK, *gV, *xt, *wt, *ct;
    cudaGetSymbolAddress((void**)&gQ, g_Q);
    cudaGetSymbolAddress((void**)&gK, g_K);
    cudaGetSymbolAddress((void**)&gV, g_V);
    cudaGetSymbolAddress((void**)&xt, g_XT);
    cudaGetSymbolAddress((void**)&wt, g_WT);
    cudaGetSymbolAddress((void**)&ct, g_CT);

    const int WN = D_MODEL * D_MODEL;

    // fused prep: tf32 rounding of inputs + weight transposes + bias table
    dim3 prep_grid(4096, 1, 5);
    prep_kernel<<<prep_grid, 256>>>(query, key, value, Wq, Wk, Wv, Wo, rpe, xt, wt);

    cudaFuncSetAttribute(gemm_tf32<true>,
                         cudaFuncAttributeMaxDynamicSharedMemorySize, GSMEM_BYTES);
    cudaFuncSetAttribute(gemm_tf32<false>,
                         cudaFuncAttributeMaxDynamicSharedMemorySize, GSMEM_BYTES);

    // fused Q/K/V projections (one launch, grid.z = matrix)
    dim3 pgrid(D_MODEL / 128, S_LEN / 128, 3);
    const float qscale = 0.125f * LOG2E;
    gemm_tf32<true><<<pgrid, 256, GSMEM_BYTES>>>(
        xt, wt, bq, bk, bv, gQ, gK, gV, qscale);

    size_t fsmem = F_FLOATS * sizeof(float);
    cudaFuncSetAttribute(flash_mma_kernel, cudaFuncAttributeMaxDynamicSharedMemorySize,
                         (int)fsmem);
    dim3 fgrid(NUM_HEADS, S_LEN / 128);   // head-fastest: global big-first order
    flash_mma_kernel<<<fgrid, 256, fsmem>>>(ct);

    // output projection
    dim3 ogrid(D_MODEL / 128, S_LEN / 128, 1);
    gemm_tf32<false><<<ogrid, 256, GSMEM_BYTES>>>(
        ct, wt + 3 * WN, bo, bo, bo, out, out, out, 1.0f);
    (void)in_sizes; (void)n_in; (void)out_size;
}